// round 12
// baseline (speedup 1.0000x reference)
#include <cuda_runtime.h>
#include <math.h>

#define BB 128
#define RR 1152
#define CC 16
#define COO 256          // C*O
#define II 8
#define RPB 8            // r per block
#define NBLK (RR / RPB)  // 144

typedef unsigned long long ull;

// ---- packed f32x2 helpers (sm_103a FFMA2; PTX-only path) ----
__device__ __forceinline__ ull fma2(ull a, ull b, ull c) {
    ull d; asm("fma.rn.f32x2 %0, %1, %2, %3;" : "=l"(d) : "l"(a), "l"(b), "l"(c)); return d;
}
__device__ __forceinline__ ull pack2(float lo, float hi) {
    ull r; asm("mov.b64 %0, {%1, %2};" : "=l"(r) : "f"(lo), "f"(hi)); return r;
}
__device__ __forceinline__ void unpack2(ull p, float& lo, float& hi) {
    asm("mov.b64 {%0, %1}, %2;" : "=f"(lo), "=f"(hi) : "l"(p));
}

// ---- globals ----
__device__ float g_spart[NBLK * BB * COO];  // s partials [p][b][co] ~18.9MB
__device__ float g_zpart[NBLK * CC];        // Z partials
__device__ float g_v[BB * COO];             // current v [b][co]
__device__ unsigned g_count;                // barrier arrivals (returns to 0)
__device__ unsigned g_sense;                // monotonic across launches

// Software grid barrier (144 CTAs, 1/SM, all co-resident). Polling via
// ld.relaxed.gpu (concurrent L2 reads) instead of serialized atomic RMW.
__device__ __forceinline__ void gridbar(unsigned& sense) {
    __threadfence();
    __syncthreads();
    if (threadIdx.x == 0) {
        sense++;
        if (atomicAdd(&g_count, 1u) == NBLK - 1u) {
            g_count = 0;
            __threadfence();
            atomicExch(&g_sense, sense);
        } else {
            unsigned s;
            do {
                asm volatile("ld.relaxed.gpu.u32 %0, [%1];" : "=r"(s) : "l"(&g_sense));
            } while (s != sense);
        }
        __threadfence();
    }
    __syncthreads();
}

// smem layout (float offsets)
#define OFF_V   0        // [b][co]              32768
#define OFF_XA  32768    // [rl][b][i]            8192  (Phase A: ull i-pairs)
#define OFF_XS  40960    // [rl][i][b]            8192  (Phase S: float4 b-quads)
#define OFF_W   49152    // 2 x [i][co] buffers   4096  (e-premult, per-rl double buf)
#define OFF_E   53248    // [rl][c]                128
#define OFF_A   53376    // [rl][c]                128
#define OFF_B2  53504    // [rl][c]                128
#define SMEM_FLOATS 53632                        // 214528 B

// ---------------------------------------------------------------------------
// Persistent kernel: 3 routing iterations, grid 144 x 1024.
// ---------------------------------------------------------------------------
__global__ void __launch_bounds__(1024, 1) k_persist(const float* __restrict__ x,
                                                     const float* __restrict__ W,
                                                     float* __restrict__ out) {
    extern __shared__ float sm[];
    float* v_sm  = sm + OFF_V;
    float* xA    = sm + OFF_XA;
    float* xS    = sm + OFF_XS;
    float* w_sm  = sm + OFF_W;
    float* e_sm  = sm + OFF_E;
    float* a_sm  = sm + OFF_A;
    float* b2_sm = sm + OFF_B2;

    int t   = threadIdx.x;
    int blk = blockIdx.x;
    int r0  = blk * RPB;

    unsigned sense = 0;
    if (t == 0) sense = atomicAdd(&g_sense, 0u);

    // stage x once into BOTH layouts
    for (int j = t; j < RPB * BB * II; j += 1024) {
        int rl = j >> 10, rem = j & 1023;          // rem = b*8 + i
        int b = rem >> 3, i = rem & 7;
        float xv = x[((size_t)b * RR + r0 + rl) * II + i];
        xA[j] = xv;
        xS[rl * 1024 + i * 128 + b] = xv;
    }
    __syncthreads();

    // Phase A decomposition: coq = co-quad, bq = b-octet
    int coq = t & 63;            // co = coq*4 .. +3
    int bq  = t >> 6;            // b  = bq*8  .. +8
    int co0 = coq * 4;
    int cA  = coq >> 2;          // capsule for this quad (uniform over quad)
    int b0A = bq * 8;

    // Phase S decomposition
    int wid  = t >> 5;           // b base = wid*4
    int lane = t & 31;           // copair = lane + 32j -> co = 2*copair

    for (int it = 0; it < 3; it++) {
        // ---------------- Phase A (agreement) ----------------
        if (it == 0) {
            if (t < RPB * CC) e_sm[t] = 1.f;
            __syncthreads();
        } else {
            for (int j = t; j < BB * COO / 4; j += 1024)
                ((float4*)v_sm)[j] = __ldcg(&((const float4*)g_v)[j]);
            if (t < RPB * CC) a_sm[t] = 0.f;
            __syncthreads();

            for (int rl = 0; rl < RPB; rl++) {
                int r = r0 + rl;
                ull G2[4][4];    // [co_l][i-pair]
#pragma unroll
                for (int cl = 0; cl < 4; cl++)
#pragma unroll
                    for (int k = 0; k < 4; k++) G2[cl][k] = 0ULL;

                const float* xr = &xA[rl * 1024];
#pragma unroll
                for (int bb = 0; bb < 8; bb++) {
                    int b = b0A + bb;
                    float4 v4 = *(const float4*)&v_sm[b * COO + co0];   // 4 wf coalesced
                    ulonglong2 xlo = *(const ulonglong2*)&xr[b * 8];    // bcast, 1 wf
                    ulonglong2 xhi = *(const ulonglong2*)&xr[b * 8 + 4];
                    ull vv;
                    vv = pack2(v4.x, v4.x);
                    G2[0][0] = fma2(xlo.x, vv, G2[0][0]);
                    G2[0][1] = fma2(xlo.y, vv, G2[0][1]);
                    G2[0][2] = fma2(xhi.x, vv, G2[0][2]);
                    G2[0][3] = fma2(xhi.y, vv, G2[0][3]);
                    vv = pack2(v4.y, v4.y);
                    G2[1][0] = fma2(xlo.x, vv, G2[1][0]);
                    G2[1][1] = fma2(xlo.y, vv, G2[1][1]);
                    G2[1][2] = fma2(xhi.x, vv, G2[1][2]);
                    G2[1][3] = fma2(xhi.y, vv, G2[1][3]);
                    vv = pack2(v4.z, v4.z);
                    G2[2][0] = fma2(xlo.x, vv, G2[2][0]);
                    G2[2][1] = fma2(xlo.y, vv, G2[2][1]);
                    G2[2][2] = fma2(xhi.x, vv, G2[2][2]);
                    G2[2][3] = fma2(xhi.y, vv, G2[2][3]);
                    vv = pack2(v4.w, v4.w);
                    G2[3][0] = fma2(xlo.x, vv, G2[3][0]);
                    G2[3][1] = fma2(xlo.y, vv, G2[3][1]);
                    G2[3][2] = fma2(xhi.x, vv, G2[3][2]);
                    G2[3][3] = fma2(xhi.y, vv, G2[3][3]);
                }
                // W-dot: ap = sum_{co in quad, i} W[r,co,i] * G[i][co]
                const ull* wp = (const ull*)&W[((size_t)r * COO + co0) * II];
                float ap = 0.f;
#pragma unroll
                for (int cl = 0; cl < 4; cl++) {
                    ull s2 = 0ULL;
                    s2 = fma2(wp[cl * 4 + 0], G2[cl][0], s2);
                    s2 = fma2(wp[cl * 4 + 1], G2[cl][1], s2);
                    s2 = fma2(wp[cl * 4 + 2], G2[cl][2], s2);
                    s2 = fma2(wp[cl * 4 + 3], G2[cl][3], s2);
                    float lo, hi; unpack2(s2, lo, hi);
                    ap += lo + hi;
                }
                // lanes 0..3 of each quad-group share c (coq consecutive per warp)
                ap += __shfl_xor_sync(0xffffffffu, ap, 1);
                ap += __shfl_xor_sync(0xffffffffu, ap, 2);
                if ((t & 3) == 0) atomicAdd(&a_sm[rl * CC + cA], ap);
            }
            __syncthreads();

            if (t < RPB * CC) {        // t = rl*16 + c
                float bprev = (it == 1) ? 0.f : b2_sm[t];
                float bn = bprev + a_sm[t] * (1.f / (float)BB);
                if (it == 1) b2_sm[t] = bn;
                e_sm[t] = expf(bn);
            }
            __syncthreads();
            if (t < CC) {
                float z = 0.f;
#pragma unroll
                for (int rl = 0; rl < RPB; rl++) z += e_sm[rl * CC + t];
                g_zpart[blk * CC + t] = z;
            }
        }

        // ---------------- Phase S with per-rl double-buffered W ----------------
        // stage_w(rl, buf): wbuf[i*256+co] = e[rl][c] * W[r0+rl][co][i]
        {
            // stage rl=0 into buf 0
            if (t < 512) {
                int co = t >> 1, i0 = (t & 1) * 4;
                float4 wv = *(const float4*)&W[((size_t)r0 * COO + co) * II + i0];
                float e = e_sm[(co >> 4)];                 // rl=0
                float* wd = &w_sm[i0 * 256 + co];
                wd[0]   = wv.x * e;
                wd[256] = wv.y * e;
                wd[512] = wv.z * e;
                wd[768] = wv.w * e;
            }
            __syncthreads();

            ull acc[4][4];
#pragma unroll
            for (int bl = 0; bl < 4; bl++)
#pragma unroll
                for (int j = 0; j < 4; j++) acc[bl][j] = 0ULL;

            for (int rl = 0; rl < RPB; rl++) {
                // prefetch next rl's W into the other buffer
                if (rl < RPB - 1 && t < 512) {
                    int co = t >> 1, i0 = (t & 1) * 4;
                    float4 wv = *(const float4*)&W[((size_t)(r0 + rl + 1) * COO + co) * II + i0];
                    float e = e_sm[(rl + 1) * CC + (co >> 4)];
                    float* wd = &w_sm[((rl + 1) & 1) * 2048 + i0 * 256 + co];
                    wd[0]   = wv.x * e;
                    wd[256] = wv.y * e;
                    wd[512] = wv.z * e;
                    wd[768] = wv.w * e;
                }
                const float* wb  = &w_sm[(rl & 1) * 2048];
                const float* x2r = &xS[rl * 1024];
#pragma unroll
                for (int i = 0; i < II; i++) {
                    const ull* wp = (const ull*)&wb[i * 256];
                    ull w0 = wp[lane], w1 = wp[lane + 32], w2 = wp[lane + 64], w3 = wp[lane + 96];
                    float4 x4 = *(const float4*)&x2r[i * 128 + wid * 4];   // bcast, 1 wf
                    ull xa = pack2(x4.x, x4.x);
                    ull xb = pack2(x4.y, x4.y);
                    ull xc = pack2(x4.z, x4.z);
                    ull xd = pack2(x4.w, x4.w);
                    acc[0][0] = fma2(xa, w0, acc[0][0]);
                    acc[0][1] = fma2(xa, w1, acc[0][1]);
                    acc[0][2] = fma2(xa, w2, acc[0][2]);
                    acc[0][3] = fma2(xa, w3, acc[0][3]);
                    acc[1][0] = fma2(xb, w0, acc[1][0]);
                    acc[1][1] = fma2(xb, w1, acc[1][1]);
                    acc[1][2] = fma2(xb, w2, acc[1][2]);
                    acc[1][3] = fma2(xb, w3, acc[1][3]);
                    acc[2][0] = fma2(xc, w0, acc[2][0]);
                    acc[2][1] = fma2(xc, w1, acc[2][1]);
                    acc[2][2] = fma2(xc, w2, acc[2][2]);
                    acc[2][3] = fma2(xc, w3, acc[2][3]);
                    acc[3][0] = fma2(xd, w0, acc[3][0]);
                    acc[3][1] = fma2(xd, w1, acc[3][1]);
                    acc[3][2] = fma2(xd, w2, acc[3][2]);
                    acc[3][3] = fma2(xd, w3, acc[3][3]);
                }
                __syncthreads();
            }
            float* sp = &g_spart[(size_t)blk * (BB * COO)];
#pragma unroll
            for (int bl = 0; bl < 4; bl++) {
                int b = wid * 4 + bl;
#pragma unroll
                for (int j = 0; j < 4; j++)
                    *(ull*)&sp[(size_t)b * COO + 2 * (lane + 32 * j)] = acc[bl][j];
            }
        }

        gridbar(sense);

        // ---------------- reduce + squash ----------------
        if (t < CC) {
            float z;
            if (it == 0) {
                z = (float)RR;
            } else {
                z = 0.f;
#pragma unroll 8
                for (int p = 0; p < NBLK; p++) z += __ldcg(&g_zpart[p * CC + t]);
            }
            a_sm[t] = z;
        }
        // 4-way split partial sums into w_sm scratch (restaged next iter)
        {
            int g = t >> 8, tt = t & 255;
            float s = 0.f;
            if (tt < 228) {
                int idx = blk * 228 + tt;
                if (idx < BB * COO) {
                    int p0 = g * 36;
#pragma unroll 9
                    for (int p = p0; p < p0 + 36; p++)
                        s += __ldcg(&g_spart[(size_t)p * (BB * COO) + idx]);
                }
            }
            w_sm[g * 256 + tt] = s;
        }
        __syncthreads();

        if (t < 228) {
            int idx = blk * 228 + t;
            if (idx < BB * COO) {
                float s = w_sm[t] + w_sm[256 + t] + w_sm[512 + t] + w_sm[768 + t];
                int c = (idx >> 4) & 15;
                s /= a_sm[c];
                float sn = s * s;
                float v = sn * s / ((1.f + sn) * sqrtf(sn));
                if (it == 2) out[idx] = v;
                else         g_v[idx] = v;
            }
        }

        if (it < 2) gridbar(sense);
    }
}

// ---------------------------------------------------------------------------
extern "C" void kernel_launch(void* const* d_in, const int* in_sizes, int n_in,
                              void* d_out, int out_size) {
    const float* x = (const float*)d_in[0];   // [128,1152,8]
    const float* W = (const float*)d_in[1];   // [1,1152,16,16,8]
    float* out = (float*)d_out;               // [128,16,16]

    const int smem = SMEM_FLOATS * (int)sizeof(float);   // ~214.5KB
    cudaFuncSetAttribute(k_persist, cudaFuncAttributeMaxDynamicSharedMemorySize, smem);
    k_persist<<<NBLK, 1024, smem>>>(x, W, out);
}

// round 13
// speedup vs baseline: 1.7139x; 1.7139x over previous
#include <cuda_runtime.h>
#include <math.h>

#define BB 128
#define RR 1152
#define CC 16
#define COO 256          // C*O
#define II 8
#define RPB 8            // r per block
#define NBLK (RR / RPB)  // 144

typedef unsigned long long ull;

// ---- packed f32x2 helpers (sm_103a FFMA2; PTX-only path) ----
__device__ __forceinline__ ull fma2(ull a, ull b, ull c) {
    ull d; asm("fma.rn.f32x2 %0, %1, %2, %3;" : "=l"(d) : "l"(a), "l"(b), "l"(c)); return d;
}
__device__ __forceinline__ ull pack2(float lo, float hi) {
    ull r; asm("mov.b64 %0, {%1, %2};" : "=l"(r) : "f"(lo), "f"(hi)); return r;
}
__device__ __forceinline__ void unpack2(ull p, float& lo, float& hi) {
    asm("mov.b64 {%0, %1}, %2;" : "=f"(lo), "=f"(hi) : "l"(p));
}

// ---- globals ----
__device__ float g_spart[NBLK * BB * COO];  // s partials [p][b][co] ~18.9MB
__device__ float g_zpart[NBLK * CC];        // Z partials
__device__ float g_v[BB * COO];             // current v [b][co]
__device__ unsigned g_count;
__device__ unsigned g_sense;

// Software grid barrier (144 CTAs, 1/SM, all co-resident).
__device__ __forceinline__ void gridbar(unsigned& sense) {
    __threadfence();
    __syncthreads();
    if (threadIdx.x == 0) {
        sense++;
        if (atomicAdd(&g_count, 1u) == NBLK - 1u) {
            g_count = 0;
            __threadfence();
            atomicExch(&g_sense, sense);
        } else {
            unsigned s;
            do {
                asm volatile("ld.relaxed.gpu.u32 %0, [%1];" : "=r"(s) : "l"(&g_sense));
            } while (s != sense);
        }
        __threadfence();
    }
    __syncthreads();
}

// smem layout (float offsets). DYN region is time-multiplexed:
//   Phase A: v[b][co] (32768)   Phase S: wT[rl][i][co] e-premult (16384)
//   reduce: 4x256 scratch
#define OFF_XA  0        // xA[rl][b][i]   8192  (Phase A: i-pair ull broadcasts)
#define OFF_XS  8192     // xS[rl][i][b]   8192  (Phase S: float4 b-quad broadcasts)
#define OFF_DYN 16384    // 32768
#define OFF_E   49152    // e_sm[rl][c]     128
#define OFF_A   49280    // a_sm[rl][c]     128  (also Z[c] scratch in reduce)
#define OFF_B2  49408    // b2_sm[rl][c]    128
#define SMEM_FLOATS 49536                 // 198144 B

// ---------------------------------------------------------------------------
// Persistent kernel: 3 routing iterations, grid 144 x 1024.
// ---------------------------------------------------------------------------
__global__ void __launch_bounds__(1024, 1) k_persist(const float* __restrict__ x,
                                                     const float* __restrict__ W,
                                                     float* __restrict__ out) {
    extern __shared__ float sm[];
    float* xA    = sm + OFF_XA;
    float* xS    = sm + OFF_XS;
    float* dyn   = sm + OFF_DYN;
    float* e_sm  = sm + OFF_E;
    float* a_sm  = sm + OFF_A;
    float* b2_sm = sm + OFF_B2;

    int t   = threadIdx.x;
    int blk = blockIdx.x;
    int r0  = blk * RPB;

    unsigned sense = 0;
    if (t == 0) sense = atomicAdd(&g_sense, 0u);

    // stage x once into BOTH layouts
    for (int j = t; j < RPB * BB * II; j += 1024) {
        int rl = j >> 10, rem = j & 1023;          // rem = b*8 + i
        int b = rem >> 3, i = rem & 7;
        float xv = x[((size_t)b * RR + r0 + rl) * II + i];
        xA[j] = xv;
        xS[rl * 1024 + i * 128 + b] = xv;
    }
    __syncthreads();

    // Phase A decomposition: thread = co-pair (128) x b-16 (8 groups)
    int pA   = t & 127;          // co-pair index -> co = 2*pA, 2*pA+1
    int octA = t >> 7;           // b block: b = octA*16 .. +15
    int co0A = 2 * pA;
    int cA   = pA >> 3;          // capsule (uniform over 8 consecutive lanes)
    int b0A  = octA * 16;

    // Phase S decomposition (R11 mapping: coalesced ull stores)
    int wid  = t >> 5;           // b base = wid*4
    int lane = t & 31;           // copair = lane + 32j -> co = 2*copair

    for (int it = 0; it < 3; it++) {
        // ---------------- Phase A (agreement) ----------------
        if (it == 0) {
            if (t < RPB * CC) e_sm[t] = 1.f;
            __syncthreads();
        } else {
            // stage v into DYN (written by other SMs -> bypass L1)
            for (int j = t; j < BB * COO / 4; j += 1024)
                ((float4*)dyn)[j] = __ldcg(&((const float4*)g_v)[j]);
            if (t < RPB * CC) a_sm[t] = 0.f;
            __syncthreads();

            for (int rl = 0; rl < RPB; rl++) {
                int r = r0 + rl;
                ull G00 = 0, G01 = 0, G02 = 0, G03 = 0;
                ull G10 = 0, G11 = 0, G12 = 0, G13 = 0;
                const float* xr = &xA[rl * 1024];
#pragma unroll 4
                for (int bb = 0; bb < 16; bb++) {
                    int b = b0A + bb;
                    ull v2 = *(const ull*)&dyn[b * COO + co0A];      // 2 wf coalesced
                    float v0, v1; unpack2(v2, v0, v1);
                    ulonglong2 xlo = *(const ulonglong2*)&xr[b * 8]; // bcast 1 wf
                    ulonglong2 xhi = *(const ulonglong2*)&xr[b * 8 + 4];
                    ull vv0 = pack2(v0, v0), vv1 = pack2(v1, v1);
                    G00 = fma2(xlo.x, vv0, G00);
                    G01 = fma2(xlo.y, vv0, G01);
                    G02 = fma2(xhi.x, vv0, G02);
                    G03 = fma2(xhi.y, vv0, G03);
                    G10 = fma2(xlo.x, vv1, G10);
                    G11 = fma2(xlo.y, vv1, G11);
                    G12 = fma2(xhi.x, vv1, G12);
                    G13 = fma2(xhi.y, vv1, G13);
                }
                // W-dot: 16 floats (co-pair x 8i), contiguous, L1-cached
                const ull* wp = (const ull*)&W[((size_t)r * COO + co0A) * II];
                ull s2 = 0ULL;
                s2 = fma2(wp[0], G00, s2);
                s2 = fma2(wp[1], G01, s2);
                s2 = fma2(wp[2], G02, s2);
                s2 = fma2(wp[3], G03, s2);
                s2 = fma2(wp[4], G10, s2);
                s2 = fma2(wp[5], G11, s2);
                s2 = fma2(wp[6], G12, s2);
                s2 = fma2(wp[7], G13, s2);
                float lo, hi; unpack2(s2, lo, hi);
                float ap = lo + hi;
                ap += __shfl_xor_sync(0xffffffffu, ap, 1);
                ap += __shfl_xor_sync(0xffffffffu, ap, 2);
                ap += __shfl_xor_sync(0xffffffffu, ap, 4);
                if ((t & 7) == 0) atomicAdd(&a_sm[rl * CC + cA], ap);
            }
            __syncthreads();

            if (t < RPB * CC) {        // t = rl*16 + c
                float bprev = (it == 1) ? 0.f : b2_sm[t];
                float bn = bprev + a_sm[t] * (1.f / (float)BB);
                if (it == 1) b2_sm[t] = bn;
                e_sm[t] = expf(bn);
            }
            __syncthreads();
            if (t < CC) {
                float z = 0.f;
#pragma unroll
                for (int rl = 0; rl < RPB; rl++) z += e_sm[rl * CC + t];
                g_zpart[blk * CC + t] = z;
            }
        }

        // ---------------- stage e-premultiplied W-transpose into DYN ----------------
        for (int q = t; q < RPB * 512; q += 1024) {
            int rl = q >> 9, k = q & 511;
            int co = k >> 1, i0 = (k & 1) * 4;
            float4 wv = *(const float4*)&W[((size_t)(r0 + rl) * COO + co) * II + i0];
            float e = e_sm[rl * CC + (co >> 4)];
            float* wd = &dyn[rl * 2048 + i0 * 256 + co];
            wd[0]   = wv.x * e;
            wd[256] = wv.y * e;
            wd[512] = wv.z * e;
            wd[768] = wv.w * e;
        }
        __syncthreads();

        // ---------------- Phase S ----------------
        {
            ull acc[4][4];
#pragma unroll
            for (int bl = 0; bl < 4; bl++)
#pragma unroll
                for (int j = 0; j < 4; j++) acc[bl][j] = 0ULL;

            for (int rl = 0; rl < RPB; rl++) {
                const float* xr = &xS[rl * 1024];
                const float* wr = &dyn[rl * 2048];
#pragma unroll
                for (int i = 0; i < II; i++) {
                    const ull* wp = (const ull*)&wr[i * 256];
                    ull w0 = wp[lane], w1 = wp[lane + 32], w2 = wp[lane + 64], w3 = wp[lane + 96];
                    float4 x4 = *(const float4*)&xr[i * 128 + wid * 4];  // bcast 1 wf
                    ull xa = pack2(x4.x, x4.x);
                    ull xb = pack2(x4.y, x4.y);
                    ull xc = pack2(x4.z, x4.z);
                    ull xd = pack2(x4.w, x4.w);
                    acc[0][0] = fma2(xa, w0, acc[0][0]);
                    acc[0][1] = fma2(xa, w1, acc[0][1]);
                    acc[0][2] = fma2(xa, w2, acc[0][2]);
                    acc[0][3] = fma2(xa, w3, acc[0][3]);
                    acc[1][0] = fma2(xb, w0, acc[1][0]);
                    acc[1][1] = fma2(xb, w1, acc[1][1]);
                    acc[1][2] = fma2(xb, w2, acc[1][2]);
                    acc[1][3] = fma2(xb, w3, acc[1][3]);
                    acc[2][0] = fma2(xc, w0, acc[2][0]);
                    acc[2][1] = fma2(xc, w1, acc[2][1]);
                    acc[2][2] = fma2(xc, w2, acc[2][2]);
                    acc[2][3] = fma2(xc, w3, acc[2][3]);
                    acc[3][0] = fma2(xd, w0, acc[3][0]);
                    acc[3][1] = fma2(xd, w1, acc[3][1]);
                    acc[3][2] = fma2(xd, w2, acc[3][2]);
                    acc[3][3] = fma2(xd, w3, acc[3][3]);
                }
            }
            float* sp = &g_spart[(size_t)blk * (BB * COO)];
#pragma unroll
            for (int bl = 0; bl < 4; bl++) {
                int b = wid * 4 + bl;
#pragma unroll
                for (int j = 0; j < 4; j++)
                    *(ull*)&sp[(size_t)b * COO + 2 * (lane + 32 * j)] = acc[bl][j];
            }
        }

        gridbar(sense);

        // ---------------- reduce + squash (DYN free: use as scratch) ----------------
        if (t < CC) {
            float z;
            if (it == 0) {
                z = (float)RR;
            } else {
                z = 0.f;
#pragma unroll 8
                for (int p = 0; p < NBLK; p++) z += __ldcg(&g_zpart[p * CC + t]);
            }
            a_sm[t] = z;
        }
        {
            int g = t >> 8, tt = t & 255;
            float s = 0.f;
            if (tt < 228) {
                int idx = blk * 228 + tt;
                if (idx < BB * COO) {
                    int p0 = g * 36;
#pragma unroll 9
                    for (int p = p0; p < p0 + 36; p++)
                        s += __ldcg(&g_spart[(size_t)p * (BB * COO) + idx]);
                }
            }
            dyn[g * 256 + tt] = s;
        }
        __syncthreads();

        if (t < 228) {
            int idx = blk * 228 + t;
            if (idx < BB * COO) {
                float s = dyn[t] + dyn[256 + t] + dyn[512 + t] + dyn[768 + t];
                int c = (idx >> 4) & 15;
                s /= a_sm[c];
                float sn = s * s;
                float v = sn * s / ((1.f + sn) * sqrtf(sn));
                if (it == 2) out[idx] = v;
                else         g_v[idx] = v;
            }
        }

        if (it < 2) gridbar(sense);
    }
}

// ---------------------------------------------------------------------------
extern "C" void kernel_launch(void* const* d_in, const int* in_sizes, int n_in,
                              void* d_out, int out_size) {
    const float* x = (const float*)d_in[0];   // [128,1152,8]
    const float* W = (const float*)d_in[1];   // [1,1152,16,16,8]
    float* out = (float*)d_out;               // [128,16,16]

    const int smem = SMEM_FLOATS * (int)sizeof(float);   // ~193.5KB
    cudaFuncSetAttribute(k_persist, cudaFuncAttributeMaxDynamicSharedMemorySize, smem);
    k_persist<<<NBLK, 1024, smem>>>(x, W, out);
}

// round 15
// speedup vs baseline: 1.9131x; 1.1162x over previous
#include <cuda_runtime.h>
#include <cuda_bf16.h>
#include <math.h>

#define BB 128
#define RR 1152
#define CC 16
#define COO 256          // C*O
#define II 8
#define RPB 8            // r per block
#define NBLK (RR / RPB)  // 144

typedef unsigned long long ull;
typedef unsigned int u32;

// ---- packed f32x2 helpers ----
__device__ __forceinline__ ull fma2(ull a, ull b, ull c) {
    ull d; asm("fma.rn.f32x2 %0, %1, %2, %3;" : "=l"(d) : "l"(a), "l"(b), "l"(c)); return d;
}
__device__ __forceinline__ ull pack2(float lo, float hi) {
    ull r; asm("mov.b64 %0, {%1, %2};" : "=l"(r) : "f"(lo), "f"(hi)); return r;
}
__device__ __forceinline__ void unpack2(ull p, float& lo, float& hi) {
    asm("mov.b64 {%0, %1}, %2;" : "=f"(lo), "=f"(hi) : "l"(p));
}
// pack two fp32 -> bf16x2 ({lo=a, hi=b})
__device__ __forceinline__ u32 bf16x2(float a, float b) {
    u32 r; asm("cvt.rn.bf16x2.f32 %0, %1, %2;" : "=r"(r) : "f"(b), "f"(a)); return r;
}
// m16n8k16 row.col bf16 MMA, D=C (fp32 accum)
__device__ __forceinline__ void mma16816(float* d, u32 a0, u32 a1, u32 a2, u32 a3,
                                         u32 b0, u32 b1) {
    asm volatile(
        "mma.sync.aligned.m16n8k16.row.col.f32.bf16.bf16.f32 "
        "{%0,%1,%2,%3}, {%4,%5,%6,%7}, {%8,%9}, {%0,%1,%2,%3};"
        : "+f"(d[0]), "+f"(d[1]), "+f"(d[2]), "+f"(d[3])
        : "r"(a0), "r"(a1), "r"(a2), "r"(a3), "r"(b0), "r"(b1));
}

// ---- globals ----
__device__ float g_spart[NBLK * BB * COO];  // [p][b][co] ~18.9MB
__device__ float g_zpart[NBLK * CC];
__device__ float g_v[BB * COO];             // v [b][co]
__device__ unsigned g_count;
__device__ unsigned g_sense;

__device__ __forceinline__ void gridbar(unsigned& sense) {
    __threadfence();
    __syncthreads();
    if (threadIdx.x == 0) {
        sense++;
        if (atomicAdd(&g_count, 1u) == NBLK - 1u) {
            g_count = 0;
            __threadfence();
            atomicExch(&g_sense, sense);
        } else {
            unsigned s;
            do { asm volatile("ld.relaxed.gpu.u32 %0, [%1];" : "=r"(s) : "l"(&g_sense)); }
            while (s != sense);
        }
        __threadfence();
    }
    __syncthreads();
}

// smem layout: float offsets / byte offsets.
// bf16 tiles use 144B row pitch: bank = (4*row + t) % 32 -> conflict-free frags.
#define OFF_XA   0        // xA[rl][b][i] fp32   8192 fl  (Phase A)
#define OFF_XH   8192     // X bf16-hi [b][k]    4608 fl (18432 B, pitch 144)
#define OFF_XL   12800    // X bf16-lo           4608 fl
#define OFF_DYN  17408    // 32768 fl: Phase A v / B tiles / reduce scratch
#define OFF_E    50176    // e_sm[rl][c]   128
#define OFF_A    50304    // a_sm[rl][c]   128 (Z scratch in reduce)
#define OFF_B2   50432    // b2_sm[rl][c]  128
#define SMEM_FLOATS 50560 // 202240 B
#define XH_BYTE  32768
#define XL_BYTE  51200
#define BH_BYTE  69632    // dyn start: eW bf16-hi [co][k] pitch 144 (36864 B)
#define BL_BYTE  106496   // eW bf16-lo

__global__ void __launch_bounds__(1024, 1) k_persist(const float* __restrict__ x,
                                                     const float* __restrict__ W,
                                                     float* __restrict__ out) {
    extern __shared__ float sm[];
    float* xA    = sm + OFF_XA;
    float* dyn   = sm + OFF_DYN;
    float* e_sm  = sm + OFF_E;
    float* a_sm  = sm + OFF_A;
    float* b2_sm = sm + OFF_B2;
    char*  smc   = (char*)sm;

    int t    = threadIdx.x;
    int wid  = t >> 5;
    int lane = t & 31;
    int blk  = blockIdx.x;
    int r0   = blk * RPB;

    unsigned sense = 0;
    if (t == 0) sense = atomicAdd(&g_sense, 0u);

    // stage xA (fp32, Phase A) and X bf16 hi/lo tiles [b][k], pitch 144B
    for (int j = t; j < RPB * BB * II; j += 1024) {
        int rl = j >> 10, rem = j & 1023;          // rem = b*8 + i
        xA[j] = x[((size_t)(rem >> 3) * RR + r0 + rl) * II + (rem & 7)];
    }
    for (int j = t; j < BB * 32; j += 1024) {      // b x k-pairs
        int b = j >> 5, k0 = (j & 31) * 2;
        int rl = k0 >> 3, i0 = k0 & 7;
        float v0 = x[((size_t)b * RR + r0 + rl) * II + i0];
        float v1 = x[((size_t)b * RR + r0 + rl) * II + i0 + 1];
        float h0 = __bfloat162float(__float2bfloat16(v0));
        float h1 = __bfloat162float(__float2bfloat16(v1));
        u32 off = (u32)(b * 144 + k0 * 2);
        *(u32*)(smc + XH_BYTE + off) = bf16x2(h0, h1);
        *(u32*)(smc + XL_BYTE + off) = bf16x2(v0 - h0, v1 - h1);
    }
    __syncthreads();

    // Phase A decomposition (R13)
    int pA   = t & 127;
    int octA = t >> 7;
    int co0A = 2 * pA;
    int cA   = pA >> 3;
    int b0A  = octA * 16;

    // Phase S warp tiling: 8 M-strips x 4 N-groups
    int ms = wid >> 2;            // b rows = ms*16 ..
    int ng = wid & 3;             // co base = ng*64
    int g  = lane >> 2, tt4 = lane & 3;

    for (int it = 0; it < 3; it++) {
        // ---------------- Phase A ----------------
        if (it == 0) {
            if (t < RPB * CC) e_sm[t] = 1.f;
            __syncthreads();
        } else {
            for (int j = t; j < BB * COO / 4; j += 1024)
                ((float4*)dyn)[j] = __ldcg(&((const float4*)g_v)[j]);
            if (t < RPB * CC) a_sm[t] = 0.f;
            __syncthreads();

            for (int rl = 0; rl < RPB; rl++) {
                int r = r0 + rl;
                ull G00 = 0, G01 = 0, G02 = 0, G03 = 0;
                ull G10 = 0, G11 = 0, G12 = 0, G13 = 0;
                const float* xr = &xA[rl * 1024];
#pragma unroll 4
                for (int bb = 0; bb < 16; bb++) {
                    int b = b0A + bb;
                    ull v2 = *(const ull*)&dyn[b * COO + co0A];
                    float v0, v1; unpack2(v2, v0, v1);
                    ulonglong2 xlo = *(const ulonglong2*)&xr[b * 8];
                    ulonglong2 xhi = *(const ulonglong2*)&xr[b * 8 + 4];
                    ull vv0 = pack2(v0, v0), vv1 = pack2(v1, v1);
                    G00 = fma2(xlo.x, vv0, G00);
                    G01 = fma2(xlo.y, vv0, G01);
                    G02 = fma2(xhi.x, vv0, G02);
                    G03 = fma2(xhi.y, vv0, G03);
                    G10 = fma2(xlo.x, vv1, G10);
                    G11 = fma2(xlo.y, vv1, G11);
                    G12 = fma2(xhi.x, vv1, G12);
                    G13 = fma2(xhi.y, vv1, G13);
                }
                const ull* wp = (const ull*)&W[((size_t)r * COO + co0A) * II];
                ull s2 = 0ULL;
                s2 = fma2(wp[0], G00, s2);
                s2 = fma2(wp[1], G01, s2);
                s2 = fma2(wp[2], G02, s2);
                s2 = fma2(wp[3], G03, s2);
                s2 = fma2(wp[4], G10, s2);
                s2 = fma2(wp[5], G11, s2);
                s2 = fma2(wp[6], G12, s2);
                s2 = fma2(wp[7], G13, s2);
                float lo, hi; unpack2(s2, lo, hi);
                float ap = lo + hi;
                ap += __shfl_xor_sync(0xffffffffu, ap, 1);
                ap += __shfl_xor_sync(0xffffffffu, ap, 2);
                ap += __shfl_xor_sync(0xffffffffu, ap, 4);
                if ((t & 7) == 0) atomicAdd(&a_sm[rl * CC + cA], ap);
            }
            __syncthreads();

            if (t < RPB * CC) {
                float bprev = (it == 1) ? 0.f : b2_sm[t];
                float bn = bprev + a_sm[t] * (1.f / (float)BB);
                if (it == 1) b2_sm[t] = bn;
                e_sm[t] = expf(bn);
            }
            __syncthreads();
            if (t < CC) {
                float z = 0.f;
#pragma unroll
                for (int rl = 0; rl < RPB; rl++) z += e_sm[rl * CC + t];
                g_zpart[blk * CC + t] = z;
            }
        }

        // ---------------- stage eW bf16 hi/lo tiles [co][k], pitch 144B ----------------
        for (int q = t; q < RPB * 512; q += 1024) {
            int rl = q >> 9, rem = q & 511;
            int co = rem >> 1, i0 = (rem & 1) * 4;
            float4 wv = *(const float4*)&W[((size_t)(r0 + rl) * COO + co) * II + i0];
            float e = e_sm[rl * CC + (co >> 4)];
            float f0 = wv.x * e, f1 = wv.y * e, f2 = wv.z * e, f3 = wv.w * e;
            float h0 = __bfloat162float(__float2bfloat16(f0));
            float h1 = __bfloat162float(__float2bfloat16(f1));
            float h2 = __bfloat162float(__float2bfloat16(f2));
            float h3 = __bfloat162float(__float2bfloat16(f3));
            int k0 = rl * 8 + i0;
            u32 off = (u32)(co * 144 + k0 * 2);
            *(u32*)(smc + BH_BYTE + off)     = bf16x2(h0, h1);
            *(u32*)(smc + BH_BYTE + off + 4) = bf16x2(h2, h3);
            *(u32*)(smc + BL_BYTE + off)     = bf16x2(f0 - h0, f1 - h1);
            *(u32*)(smc + BL_BYTE + off + 4) = bf16x2(f2 - h2, f3 - h3);
        }
        __syncthreads();

        // ---------------- Phase S: mma.sync bf16, 3 splits x 4 k16 steps ----------------
        {
            float d[8][4];
#pragma unroll
            for (int j = 0; j < 8; j++)
#pragma unroll
                for (int k = 0; k < 4; k++) d[j][k] = 0.f;

#pragma unroll
            for (int sp = 0; sp < 3; sp++) {
                u32 ab = (sp == 2) ? XL_BYTE : XH_BYTE;
                u32 bb = (sp == 1) ? BL_BYTE : BH_BYTE;
#pragma unroll
                for (int kk = 0; kk < 4; kk++) {
                    u32 ar0 = ab + (u32)((ms * 16 + g) * 144 + kk * 32 + tt4 * 4);
                    u32 ar1 = ar0 + 8 * 144;
                    u32 a0 = *(const u32*)(smc + ar0);
                    u32 a1 = *(const u32*)(smc + ar1);
                    u32 a2 = *(const u32*)(smc + ar0 + 16);
                    u32 a3 = *(const u32*)(smc + ar1 + 16);
#pragma unroll
                    for (int j = 0; j < 8; j++) {
                        u32 bo = bb + (u32)((ng * 64 + j * 8 + g) * 144 + kk * 32 + tt4 * 4);
                        u32 b0 = *(const u32*)(smc + bo);
                        u32 b1 = *(const u32*)(smc + bo + 16);
                        mma16816(d[j], a0, a1, a2, a3, b0, b1);
                    }
                }
            }
            // store D -> spart[p][b][co]
            float* sp2 = &g_spart[(size_t)blk * (BB * COO)];
            int br = ms * 16 + g;
#pragma unroll
            for (int j = 0; j < 8; j++) {
                int co = ng * 64 + j * 8 + 2 * tt4;
                *(ull*)&sp2[(size_t)br * COO + co]       = pack2(d[j][0], d[j][1]);
                *(ull*)&sp2[(size_t)(br + 8) * COO + co] = pack2(d[j][2], d[j][3]);
            }
        }

        gridbar(sense);

        // ---------------- reduce + squash (idx = b*256 + co) ----------------
        if (t < CC) {
            float z;
            if (it == 0) z = (float)RR;
            else {
                z = 0.f;
#pragma unroll 8
                for (int p = 0; p < NBLK; p++) z += __ldcg(&g_zpart[p * CC + t]);
            }
            a_sm[t] = z;
        }
        {
            int gg = t >> 8, ti = t & 255;
            float s = 0.f;
            if (ti < 228) {
                int idx = blk * 228 + ti;
                if (idx < BB * COO) {
                    int p0 = gg * 36;
#pragma unroll 9
                    for (int p = p0; p < p0 + 36; p++)
                        s += __ldcg(&g_spart[(size_t)p * (BB * COO) + idx]);
                }
            }
            dyn[gg * 256 + ti] = s;
        }
        __syncthreads();

        if (t < 228) {
            int idx = blk * 228 + t;
            if (idx < BB * COO) {
                float s = dyn[t] + dyn[256 + t] + dyn[512 + t] + dyn[768 + t];
                int c = (idx >> 4) & 15;
                s /= a_sm[c];
                float sn = s * s;
                float v = sn * s / ((1.f + sn) * sqrtf(sn));
                if (it == 2) out[idx] = v;
                else         g_v[idx] = v;
            }
        }

        if (it < 2) gridbar(sense);
    }
}

// ---------------------------------------------------------------------------
extern "C" void kernel_launch(void* const* d_in, const int* in_sizes, int n_in,
                              void* d_out, int out_size) {
    const float* x = (const float*)d_in[0];   // [128,1152,8]
    const float* W = (const float*)d_in[1];   // [1,1152,16,16,8]
    float* out = (float*)d_out;               // [128,16,16]

    const int smem = SMEM_FLOATS * (int)sizeof(float);   // ~197.5KB
    cudaFuncSetAttribute(k_persist, cudaFuncAttributeMaxDynamicSharedMemorySize, smem);
    k_persist<<<NBLK, 1024, smem>>>(x, W, out);
}

// round 16
// speedup vs baseline: 2.5814x; 1.3493x over previous
#include <cuda_runtime.h>
#include <cuda_bf16.h>
#include <math.h>

#define BB 128
#define RR 1152
#define CC 16
#define COO 256          // C*O
#define II 8
#define RPB 8            // r per block
#define NBLK (RR / RPB)  // 144

typedef unsigned long long ull;
typedef unsigned int u32;

__device__ __forceinline__ ull pack2(float lo, float hi) {
    ull r; asm("mov.b64 %0, {%1, %2};" : "=l"(r) : "f"(lo), "f"(hi)); return r;
}
// pack two fp32 -> bf16x2 ({lo=a, hi=b})
__device__ __forceinline__ u32 bf16x2(float a, float b) {
    u32 r; asm("cvt.rn.bf16x2.f32 %0, %1, %2;" : "=r"(r) : "f"(b), "f"(a)); return r;
}
// m16n8k16 row.col bf16 MMA, D=C (fp32 accum)
__device__ __forceinline__ void mma16816(float* d, u32 a0, u32 a1, u32 a2, u32 a3,
                                         u32 b0, u32 b1) {
    asm volatile(
        "mma.sync.aligned.m16n8k16.row.col.f32.bf16.bf16.f32 "
        "{%0,%1,%2,%3}, {%4,%5,%6,%7}, {%8,%9}, {%0,%1,%2,%3};"
        : "+f"(d[0]), "+f"(d[1]), "+f"(d[2]), "+f"(d[3])
        : "r"(a0), "r"(a1), "r"(a2), "r"(a3), "r"(b0), "r"(b1));
}

// ---- globals ----
__device__ float g_spart[NBLK * BB * COO];      // [p][b][co] ~18.9MB
__device__ float g_zpart[NBLK * CC];
__device__ __nv_bfloat16 g_vh[COO * BB];        // v hi, [co][b]
__device__ __nv_bfloat16 g_vl[COO * BB];        // v lo residual, [co][b]
__device__ unsigned g_count;
__device__ unsigned g_sense;

__device__ __forceinline__ void gridbar(unsigned& sense) {
    __threadfence();
    __syncthreads();
    if (threadIdx.x == 0) {
        sense++;
        if (atomicAdd(&g_count, 1u) == NBLK - 1u) {
            g_count = 0;
            __threadfence();
            atomicExch(&g_sense, sense);
        } else {
            unsigned s;
            do { asm volatile("ld.relaxed.gpu.u32 %0, [%1];" : "=r"(s) : "l"(&g_sense)); }
            while (s != sense);
        }
        __threadfence();
    }
    __syncthreads();
}

// ---- smem byte offsets ----
#define XSH_B 0        // X bf16-hi [b][k]   pitch 144, 18432 B   (Phase S A-op)
#define XSL_B 18432    // X bf16-lo                     18432 B
#define XTH_B 36864    // X bf16-hi [k][b]   pitch 272, 17408 B   (Phase A A-op)
#define XTL_B 54272    // X bf16-lo                     17408 B
#define DYN_B 71680    // 73728 B: V-half tiles / eW tiles / reduce scratch
#define VH_B  DYN_B             // V-half hi [co_l][b] pitch 272, 34816 B
#define VL_B  (DYN_B + 34816)
#define BH_B  DYN_B             // eW hi [co][k] pitch 144, 36864 B
#define BL_B  (DYN_B + 36864)
#define G_B   145408   // G [64][132] fp32, 33792 B
#define E_B   179200   // e_sm [rl][c] 128 fl
#define A_B   179712   // a_sm [rl][c] 128 fl (Z scratch in reduce)
#define B2_B  180224   // b2_sm [rl][c] 128 fl
#define SMEM_BYTES 180736

__global__ void __launch_bounds__(1024, 1) k_persist(const float* __restrict__ x,
                                                     const float* __restrict__ W,
                                                     float* __restrict__ out) {
    extern __shared__ char smc[];
    float* dynf  = (float*)(smc + DYN_B);
    float* Gf    = (float*)(smc + G_B);
    float* e_sm  = (float*)(smc + E_B);
    float* a_sm  = (float*)(smc + A_B);
    float* b2_sm = (float*)(smc + B2_B);

    int t    = threadIdx.x;
    int wid  = t >> 5;
    int lane = t & 31;
    int blk  = blockIdx.x;
    int r0   = blk * RPB;

    unsigned sense = 0;
    if (t == 0) sense = atomicAdd(&g_sense, 0u);

    // ---- stage x once: XS [b][k] (pitch 144) and XT [k][b] (pitch 272), hi/lo ----
    for (int q = t; q < RPB * BB * 4; q += 1024) {       // (rl, b, i-pair)
        int ip = q & 3, b = (q >> 2) & 127, rl = q >> 9;
        const float* xp = &x[((size_t)b * RR + r0 + rl) * II + ip * 2];
        float v0 = xp[0], v1 = xp[1];
        __nv_bfloat16 bh0 = __float2bfloat16(v0), bh1 = __float2bfloat16(v1);
        float h0 = __bfloat162float(bh0), h1 = __bfloat162float(bh1);
        __nv_bfloat16 bl0 = __float2bfloat16(v0 - h0), bl1 = __float2bfloat16(v1 - h1);
        int k0 = rl * 8 + ip * 2;
        *(u32*)(smc + XSH_B + b * 144 + k0 * 2) = bf16x2(h0, h1);
        *(u32*)(smc + XSL_B + b * 144 + k0 * 2) = bf16x2(v0 - h0, v1 - h1);
        *(__nv_bfloat16*)(smc + XTH_B + k0 * 272 + b * 2)       = bh0;
        *(__nv_bfloat16*)(smc + XTH_B + (k0 + 1) * 272 + b * 2) = bh1;
        *(__nv_bfloat16*)(smc + XTL_B + k0 * 272 + b * 2)       = bl0;
        *(__nv_bfloat16*)(smc + XTL_B + (k0 + 1) * 272 + b * 2) = bl1;
    }
    __syncthreads();

    // frag indices
    int g   = lane >> 2, tt4 = lane & 3;
    // Phase S warp tiling (R15): 8 M-strips x 4 N-groups
    int ms  = wid >> 2, ng = wid & 3;
    // Phase A warp tiling: 4 M-strips x 8 N-groups (2 j-tiles each)
    int msA = wid >> 3, jgA = wid & 7;
    // Phase A epilogue mapping
    int oE  = t & 15, cE = (t >> 4) & 7, rlE = t >> 7;

    for (int it = 0; it < 3; it++) {
        // ================= Phase A =================
        if (it == 0) {
            if (t < RPB * CC) e_sm[t] = 1.f;
            __syncthreads();
        } else {
            for (int h = 0; h < 2; h++) {
                // stage V-half bf16 tiles [co_l][b], pitch 272
                for (int q = t; q < 8192; q += 1024) {
                    int co_l = q >> 6, bp = q & 63;
                    u32 vh = __ldcg(&((const u32*)g_vh)[(h * 128 + co_l) * 64 + bp]);
                    u32 vl = __ldcg(&((const u32*)g_vl)[(h * 128 + co_l) * 64 + bp]);
                    *(u32*)(smc + VH_B + co_l * 272 + bp * 4) = vh;
                    *(u32*)(smc + VL_B + co_l * 272 + bp * 4) = vl;
                }
                __syncthreads();

                // MMA: G[64 x 128] = XT[64 x 128b] * Vhalf^T, 3 bf16-split terms
                {
                    float dd[2][4];
#pragma unroll
                    for (int j = 0; j < 2; j++)
#pragma unroll
                        for (int k = 0; k < 4; k++) dd[j][k] = 0.f;

#pragma unroll
                    for (int sp = 0; sp < 3; sp++) {
                        u32 ab = (sp == 2) ? XTL_B : XTH_B;
                        u32 bb = (sp == 1) ? VL_B : VH_B;
#pragma unroll
                        for (int kk = 0; kk < 8; kk++) {
                            u32 ar0 = ab + (u32)((msA * 16 + g) * 272 + kk * 32 + tt4 * 4);
                            u32 a0 = *(const u32*)(smc + ar0);
                            u32 a1 = *(const u32*)(smc + ar0 + 8 * 272);
                            u32 a2 = *(const u32*)(smc + ar0 + 16);
                            u32 a3 = *(const u32*)(smc + ar0 + 8 * 272 + 16);
#pragma unroll
                            for (int jj = 0; jj < 2; jj++) {
                                int j = jgA * 2 + jj;
                                u32 bo = bb + (u32)((j * 8 + g) * 272 + kk * 32 + tt4 * 4);
                                u32 b0 = *(const u32*)(smc + bo);
                                u32 b1 = *(const u32*)(smc + bo + 16);
                                mma16816(dd[jj], a0, a1, a2, a3, b0, b1);
                            }
                        }
                    }
                    // store to G [64][132]
#pragma unroll
                    for (int jj = 0; jj < 2; jj++) {
                        int col = (jgA * 2 + jj) * 8 + tt4 * 2;
                        int row = msA * 16 + g;
                        *(ull*)&Gf[row * 132 + col]       = pack2(dd[jj][0], dd[jj][1]);
                        *(ull*)&Gf[(row + 8) * 132 + col] = pack2(dd[jj][2], dd[jj][3]);
                    }
                }
                __syncthreads();

                // epilogue: a[rl, h*8+cE] = sum_{o,i} W * G
                {
                    int co = (h * 8 + cE) * 16 + oE;
                    const float* wrow = &W[((size_t)(r0 + rlE) * COO + co) * II];
                    const float* gcol = &Gf[(rlE * 8) * 132 + cE * 16 + oE];
                    float ap = 0.f;
#pragma unroll
                    for (int i = 0; i < II; i++)
                        ap += wrow[i] * gcol[i * 132];
                    ap += __shfl_xor_sync(0xffffffffu, ap, 1);
                    ap += __shfl_xor_sync(0xffffffffu, ap, 2);
                    ap += __shfl_xor_sync(0xffffffffu, ap, 4);
                    ap += __shfl_xor_sync(0xffffffffu, ap, 8);
                    if ((t & 15) == 0) a_sm[rlE * CC + h * 8 + cE] = ap;
                }
                __syncthreads();   // protect DYN before next half / eW staging
            }

            if (t < RPB * CC) {
                float bprev = (it == 1) ? 0.f : b2_sm[t];
                float bn = bprev + a_sm[t] * (1.f / (float)BB);
                if (it == 1) b2_sm[t] = bn;
                e_sm[t] = expf(bn);
            }
            __syncthreads();
            if (t < CC) {
                float z = 0.f;
#pragma unroll
                for (int rl = 0; rl < RPB; rl++) z += e_sm[rl * CC + t];
                g_zpart[blk * CC + t] = z;
            }
        }

        // ---- stage eW bf16 hi/lo tiles [co][k], pitch 144 ----
        for (int q = t; q < RPB * 512; q += 1024) {
            int rl = q >> 9, rem = q & 511;
            int co = rem >> 1, i0 = (rem & 1) * 4;
            float4 wv = *(const float4*)&W[((size_t)(r0 + rl) * COO + co) * II + i0];
            float e = e_sm[rl * CC + (co >> 4)];
            float f0 = wv.x * e, f1 = wv.y * e, f2 = wv.z * e, f3 = wv.w * e;
            float h0 = __bfloat162float(__float2bfloat16(f0));
            float h1 = __bfloat162float(__float2bfloat16(f1));
            float h2 = __bfloat162float(__float2bfloat16(f2));
            float h3 = __bfloat162float(__float2bfloat16(f3));
            int k0 = rl * 8 + i0;
            u32 off = (u32)(co * 144 + k0 * 2);
            *(u32*)(smc + BH_B + off)     = bf16x2(h0, h1);
            *(u32*)(smc + BH_B + off + 4) = bf16x2(h2, h3);
            *(u32*)(smc + BL_B + off)     = bf16x2(f0 - h0, f1 - h1);
            *(u32*)(smc + BL_B + off + 4) = bf16x2(f2 - h2, f3 - h3);
        }
        __syncthreads();

        // ================= Phase S (R15) =================
        {
            float d[8][4];
#pragma unroll
            for (int j = 0; j < 8; j++)
#pragma unroll
                for (int k = 0; k < 4; k++) d[j][k] = 0.f;

#pragma unroll
            for (int sp = 0; sp < 3; sp++) {
                u32 ab = (sp == 2) ? XSL_B : XSH_B;
                u32 bb = (sp == 1) ? BL_B : BH_B;
#pragma unroll
                for (int kk = 0; kk < 4; kk++) {
                    u32 ar0 = ab + (u32)((ms * 16 + g) * 144 + kk * 32 + tt4 * 4);
                    u32 a0 = *(const u32*)(smc + ar0);
                    u32 a1 = *(const u32*)(smc + ar0 + 8 * 144);
                    u32 a2 = *(const u32*)(smc + ar0 + 16);
                    u32 a3 = *(const u32*)(smc + ar0 + 8 * 144 + 16);
#pragma unroll
                    for (int j = 0; j < 8; j++) {
                        u32 bo = bb + (u32)((ng * 64 + j * 8 + g) * 144 + kk * 32 + tt4 * 4);
                        u32 b0 = *(const u32*)(smc + bo);
                        u32 b1 = *(const u32*)(smc + bo + 16);
                        mma16816(d[j], a0, a1, a2, a3, b0, b1);
                    }
                }
            }
            float* sp2 = &g_spart[(size_t)blk * (BB * COO)];
            int br = ms * 16 + g;
#pragma unroll
            for (int j = 0; j < 8; j++) {
                int co = ng * 64 + j * 8 + 2 * tt4;
                *(ull*)&sp2[(size_t)br * COO + co]       = pack2(d[j][0], d[j][1]);
                *(ull*)&sp2[(size_t)(br + 8) * COO + co] = pack2(d[j][2], d[j][3]);
            }
        }

        gridbar(sense);

        // ================= reduce + squash (idx = b*256 + co) =================
        if (t < CC) {
            float z;
            if (it == 0) z = (float)RR;
            else {
                z = 0.f;
#pragma unroll 8
                for (int p = 0; p < NBLK; p++) z += __ldcg(&g_zpart[p * CC + t]);
            }
            a_sm[t] = z;
        }
        {
            int gg = t >> 8, ti = t & 255;
            float s = 0.f;
            if (ti < 228) {
                int idx = blk * 228 + ti;
                if (idx < BB * COO) {
                    int p0 = gg * 36;
#pragma unroll 9
                    for (int p = p0; p < p0 + 36; p++)
                        s += __ldcg(&g_spart[(size_t)p * (BB * COO) + idx]);
                }
            }
            dynf[gg * 256 + ti] = s;
        }
        __syncthreads();

        if (t < 228) {
            int idx = blk * 228 + t;
            if (idx < BB * COO) {
                float s = dynf[t] + dynf[256 + t] + dynf[512 + t] + dynf[768 + t];
                int c = (idx >> 4) & 15;
                s /= a_sm[c];
                float sn = s * s;
                float v = sn * s / ((1.f + sn) * sqrtf(sn));
                if (it == 2) {
                    out[idx] = v;
                } else {
                    int b = idx >> 8, co = idx & 255;
                    __nv_bfloat16 vh = __float2bfloat16(v);
                    g_vh[co * BB + b] = vh;
                    g_vl[co * BB + b] = __float2bfloat16(v - __bfloat162float(vh));
                }
            }
        }

        if (it < 2) gridbar(sense);
    }
}

// ---------------------------------------------------------------------------
extern "C" void kernel_launch(void* const* d_in, const int* in_sizes, int n_in,
                              void* d_out, int out_size) {
    const float* x = (const float*)d_in[0];   // [128,1152,8]
    const float* W = (const float*)d_in[1];   // [1,1152,16,16,8]
    float* out = (float*)d_out;               // [128,16,16]

    cudaFuncSetAttribute(k_persist, cudaFuncAttributeMaxDynamicSharedMemorySize, SMEM_BYTES);
    k_persist<<<NBLK, 1024, SMEM_BYTES>>>(x, W, out);
}

// round 17
// speedup vs baseline: 2.9607x; 1.1469x over previous
#include <cuda_runtime.h>
#include <cuda_bf16.h>
#include <math.h>

#define BB 128
#define CC 16
#define COO 256          // C*O
#define II 8
#define RPB 8            // r per block
#define RR 1152
#define NBLK (RR / RPB)  // 144

typedef unsigned long long ull;
typedef unsigned int u32;

__device__ __forceinline__ ull pack2(float lo, float hi) {
    ull r; asm("mov.b64 %0, {%1, %2};" : "=l"(r) : "f"(lo), "f"(hi)); return r;
}
// pack two fp32 -> bf16x2 ({lo=a, hi=b})
__device__ __forceinline__ u32 bf16x2(float a, float b) {
    u32 r; asm("cvt.rn.bf16x2.f32 %0, %1, %2;" : "=r"(r) : "f"(b), "f"(a)); return r;
}
// m16n8k16 row.col bf16 MMA, D=C (fp32 accum)
__device__ __forceinline__ void mma16816(float* d, u32 a0, u32 a1, u32 a2, u32 a3,
                                         u32 b0, u32 b1) {
    asm volatile(
        "mma.sync.aligned.m16n8k16.row.col.f32.bf16.bf16.f32 "
        "{%0,%1,%2,%3}, {%4,%5,%6,%7}, {%8,%9}, {%0,%1,%2,%3};"
        : "+f"(d[0]), "+f"(d[1]), "+f"(d[2]), "+f"(d[3])
        : "r"(a0), "r"(a1), "r"(a2), "r"(a3), "r"(b0), "r"(b1));
}

// ---- globals ----
__device__ float g_spart[NBLK * BB * COO];      // [p][b][co] ~18.9MB
__device__ float g_zpart[NBLK * CC];
__device__ __nv_bfloat16 g_vh[COO * BB];        // v hi, [co][b]
__device__ __nv_bfloat16 g_vl[COO * BB];        // v lo residual, [co][b]
__device__ unsigned g_count;
__device__ unsigned g_sense;

__device__ __forceinline__ void gridbar(unsigned& sense) {
    __threadfence();
    __syncthreads();
    if (threadIdx.x == 0) {
        sense++;
        if (atomicAdd(&g_count, 1u) == NBLK - 1u) {
            g_count = 0;
            __threadfence();
            atomicExch(&g_sense, sense);
        } else {
            unsigned s;
            do { asm volatile("ld.relaxed.gpu.u32 %0, [%1];" : "=r"(s) : "l"(&g_sense)); }
            while (s != sense);
        }
        __threadfence();
    }
    __syncthreads();
}

// ---- smem byte offsets ----
#define XSH_B 0        // X bf16-hi [b][k]   pitch 144, 18432 B   (Phase S A-op)
#define XSL_B 18432    // X bf16-lo                     18432 B
#define XTH_B 36864    // X bf16-hi [k][b]   pitch 272, 17408 B   (Phase A A-op)
#define XTL_B 54272    // X bf16-lo                     17408 B
#define DYN_B 71680    // 73728 B: V-half tiles / eW tiles / reduce scratch
#define VH_B  DYN_B             // V-half hi [co_l][b] pitch 272, 34816 B
#define VL_B  (DYN_B + 34816)
#define BH_B  DYN_B             // eW hi [co][k] pitch 144, 36864 B
#define BL_B  (DYN_B + 36864)
#define G_B   145408   // G [64][132] fp32, 33792 B
#define E_B   179200   // e_sm [rl][c] 128 fl
#define A_B   179712   // a_sm [rl][c] 128 fl (Z scratch in reduce)
#define B2_B  180224   // b2_sm [rl][c] 128 fl
#define SMEM_BYTES 180736

__global__ void __launch_bounds__(1024, 1) k_persist(const float* __restrict__ x,
                                                     const float* __restrict__ W,
                                                     float* __restrict__ out) {
    extern __shared__ char smc[];
    float* dynf  = (float*)(smc + DYN_B);
    float* Gf    = (float*)(smc + G_B);
    float* e_sm  = (float*)(smc + E_B);
    float* a_sm  = (float*)(smc + A_B);
    float* b2_sm = (float*)(smc + B2_B);

    int t    = threadIdx.x;
    int wid  = t >> 5;
    int lane = t & 31;
    int blk  = blockIdx.x;
    int r0   = blk * RPB;

    unsigned sense = 0;
    if (t == 0) sense = atomicAdd(&g_sense, 0u);

    // ---- stage x once: XS [b][k] (pitch 144) and XT [k][b] (pitch 272), hi/lo ----
    for (int q = t; q < RPB * BB * 4; q += 1024) {       // (rl, b, i-pair)
        int ip = q & 3, b = (q >> 2) & 127, rl = q >> 9;
        const float* xp = &x[((size_t)b * RR + r0 + rl) * II + ip * 2];
        float v0 = xp[0], v1 = xp[1];
        __nv_bfloat16 bh0 = __float2bfloat16(v0), bh1 = __float2bfloat16(v1);
        float h0 = __bfloat162float(bh0), h1 = __bfloat162float(bh1);
        __nv_bfloat16 bl0 = __float2bfloat16(v0 - h0), bl1 = __float2bfloat16(v1 - h1);
        int k0 = rl * 8 + ip * 2;
        *(u32*)(smc + XSH_B + b * 144 + k0 * 2) = bf16x2(h0, h1);
        *(u32*)(smc + XSL_B + b * 144 + k0 * 2) = bf16x2(v0 - h0, v1 - h1);
        *(__nv_bfloat16*)(smc + XTH_B + k0 * 272 + b * 2)       = bh0;
        *(__nv_bfloat16*)(smc + XTH_B + (k0 + 1) * 272 + b * 2) = bh1;
        *(__nv_bfloat16*)(smc + XTL_B + k0 * 272 + b * 2)       = bl0;
        *(__nv_bfloat16*)(smc + XTL_B + (k0 + 1) * 272 + b * 2) = bl1;
    }
    __syncthreads();

    // frag indices
    int g   = lane >> 2, tt4 = lane & 3;
    // Phase S warp tiling: 8 M-strips x 4 N-groups
    int ms  = wid >> 2, ng = wid & 3;
    // Phase A warp tiling: 4 M-strips x 8 N-groups (2 j-tiles each)
    int msA = wid >> 3, jgA = wid & 7;
    // Phase A epilogue mapping
    int oE  = t & 15, cE = (t >> 4) & 7, rlE = t >> 7;

    for (int it = 0; it < 3; it++) {
        // ================= Phase A =================
        if (it == 0) {
            if (t < RPB * CC) e_sm[t] = 1.f;
            __syncthreads();
        } else {
            for (int h = 0; h < 2; h++) {
                // stage V-half bf16 tiles [co_l][b], pitch 272
                for (int q = t; q < 8192; q += 1024) {
                    int co_l = q >> 6, bp = q & 63;
                    u32 vh = __ldcg(&((const u32*)g_vh)[(h * 128 + co_l) * 64 + bp]);
                    u32 vl = __ldcg(&((const u32*)g_vl)[(h * 128 + co_l) * 64 + bp]);
                    *(u32*)(smc + VH_B + co_l * 272 + bp * 4) = vh;
                    *(u32*)(smc + VL_B + co_l * 272 + bp * 4) = vl;
                }
                __syncthreads();

                // MMA: G[64 x 128] = XT * Vhalf^T; fused frag loads, 3 split terms
                {
                    float dd[2][4];
#pragma unroll
                    for (int j = 0; j < 2; j++)
#pragma unroll
                        for (int k = 0; k < 4; k++) dd[j][k] = 0.f;

#pragma unroll
                    for (int kk = 0; kk < 8; kk++) {
                        u32 ar = (u32)((msA * 16 + g) * 272 + kk * 32 + tt4 * 4);
                        u32 ah0 = *(const u32*)(smc + XTH_B + ar);
                        u32 ah1 = *(const u32*)(smc + XTH_B + ar + 8 * 272);
                        u32 ah2 = *(const u32*)(smc + XTH_B + ar + 16);
                        u32 ah3 = *(const u32*)(smc + XTH_B + ar + 8 * 272 + 16);
                        u32 al0 = *(const u32*)(smc + XTL_B + ar);
                        u32 al1 = *(const u32*)(smc + XTL_B + ar + 8 * 272);
                        u32 al2 = *(const u32*)(smc + XTL_B + ar + 16);
                        u32 al3 = *(const u32*)(smc + XTL_B + ar + 8 * 272 + 16);
#pragma unroll
                        for (int jj = 0; jj < 2; jj++) {
                            int j = jgA * 2 + jj;
                            u32 bo = (u32)((j * 8 + g) * 272 + kk * 32 + tt4 * 4);
                            u32 bh0 = *(const u32*)(smc + VH_B + bo);
                            u32 bh1 = *(const u32*)(smc + VH_B + bo + 16);
                            u32 bl0 = *(const u32*)(smc + VL_B + bo);
                            u32 bl1 = *(const u32*)(smc + VL_B + bo + 16);
                            mma16816(dd[jj], ah0, ah1, ah2, ah3, bh0, bh1);  // hi*hi
                            mma16816(dd[jj], ah0, ah1, ah2, ah3, bl0, bl1);  // hi*lo
                            mma16816(dd[jj], al0, al1, al2, al3, bh0, bh1);  // lo*hi
                        }
                    }
                    // store to G [64][132]
#pragma unroll
                    for (int jj = 0; jj < 2; jj++) {
                        int col = (jgA * 2 + jj) * 8 + tt4 * 2;
                        int row = msA * 16 + g;
                        *(ull*)&Gf[row * 132 + col]       = pack2(dd[jj][0], dd[jj][1]);
                        *(ull*)&Gf[(row + 8) * 132 + col] = pack2(dd[jj][2], dd[jj][3]);
                    }
                }
                __syncthreads();

                // epilogue: a[rl, h*8+cE] = sum_{o,i} W * G
                {
                    int co = (h * 8 + cE) * 16 + oE;
                    const float* wrow = &W[((size_t)(r0 + rlE) * COO + co) * II];
                    const float* gcol = &Gf[(rlE * 8) * 132 + cE * 16 + oE];
                    float ap = 0.f;
#pragma unroll
                    for (int i = 0; i < II; i++)
                        ap += wrow[i] * gcol[i * 132];
                    ap += __shfl_xor_sync(0xffffffffu, ap, 1);
                    ap += __shfl_xor_sync(0xffffffffu, ap, 2);
                    ap += __shfl_xor_sync(0xffffffffu, ap, 4);
                    ap += __shfl_xor_sync(0xffffffffu, ap, 8);
                    if ((t & 15) == 0) a_sm[rlE * CC + h * 8 + cE] = ap;
                }
                __syncthreads();   // protect DYN before next half / eW staging
            }

            if (t < RPB * CC) {
                float bprev = (it == 1) ? 0.f : b2_sm[t];
                float bn = bprev + a_sm[t] * (1.f / (float)BB);
                if (it == 1) b2_sm[t] = bn;
                e_sm[t] = expf(bn);
            }
            __syncthreads();
            if (t < CC) {
                float z = 0.f;
#pragma unroll
                for (int rl = 0; rl < RPB; rl++) z += e_sm[rl * CC + t];
                g_zpart[blk * CC + t] = z;
            }
        }

        // ---- stage eW bf16 hi/lo tiles [co][k], pitch 144 ----
        for (int q = t; q < RPB * 512; q += 1024) {
            int rl = q >> 9, rem = q & 511;
            int co = rem >> 1, i0 = (rem & 1) * 4;
            float4 wv = *(const float4*)&W[((size_t)(r0 + rl) * COO + co) * II + i0];
            float e = e_sm[rl * CC + (co >> 4)];
            float f0 = wv.x * e, f1 = wv.y * e, f2 = wv.z * e, f3 = wv.w * e;
            float h0 = __bfloat162float(__float2bfloat16(f0));
            float h1 = __bfloat162float(__float2bfloat16(f1));
            float h2 = __bfloat162float(__float2bfloat16(f2));
            float h3 = __bfloat162float(__float2bfloat16(f3));
            int k0 = rl * 8 + i0;
            u32 off = (u32)(co * 144 + k0 * 2);
            *(u32*)(smc + BH_B + off)     = bf16x2(h0, h1);
            *(u32*)(smc + BH_B + off + 4) = bf16x2(h2, h3);
            *(u32*)(smc + BL_B + off)     = bf16x2(f0 - h0, f1 - h1);
            *(u32*)(smc + BL_B + off + 4) = bf16x2(f2 - h2, f3 - h3);
        }
        __syncthreads();

        // ================= Phase S: fused frag loads, 3 split terms =================
        {
            float d[8][4];
#pragma unroll
            for (int j = 0; j < 8; j++)
#pragma unroll
                for (int k = 0; k < 4; k++) d[j][k] = 0.f;

#pragma unroll
            for (int kk = 0; kk < 4; kk++) {
                u32 ar = (u32)((ms * 16 + g) * 144 + kk * 32 + tt4 * 4);
                u32 ah0 = *(const u32*)(smc + XSH_B + ar);
                u32 ah1 = *(const u32*)(smc + XSH_B + ar + 8 * 144);
                u32 ah2 = *(const u32*)(smc + XSH_B + ar + 16);
                u32 ah3 = *(const u32*)(smc + XSH_B + ar + 8 * 144 + 16);
                u32 al0 = *(const u32*)(smc + XSL_B + ar);
                u32 al1 = *(const u32*)(smc + XSL_B + ar + 8 * 144);
                u32 al2 = *(const u32*)(smc + XSL_B + ar + 16);
                u32 al3 = *(const u32*)(smc + XSL_B + ar + 8 * 144 + 16);
#pragma unroll
                for (int j = 0; j < 8; j++) {
                    u32 bo = (u32)((ng * 64 + j * 8 + g) * 144 + kk * 32 + tt4 * 4);
                    u32 bh0 = *(const u32*)(smc + BH_B + bo);
                    u32 bh1 = *(const u32*)(smc + BH_B + bo + 16);
                    u32 bl0 = *(const u32*)(smc + BL_B + bo);
                    u32 bl1 = *(const u32*)(smc + BL_B + bo + 16);
                    mma16816(d[j], ah0, ah1, ah2, ah3, bh0, bh1);  // hi*hi
                    mma16816(d[j], ah0, ah1, ah2, ah3, bl0, bl1);  // hi*lo
                    mma16816(d[j], al0, al1, al2, al3, bh0, bh1);  // lo*hi
                }
            }
            float* sp2 = &g_spart[(size_t)blk * (BB * COO)];
            int br = ms * 16 + g;
#pragma unroll
            for (int j = 0; j < 8; j++) {
                int co = ng * 64 + j * 8 + 2 * tt4;
                *(ull*)&sp2[(size_t)br * COO + co]       = pack2(d[j][0], d[j][1]);
                *(ull*)&sp2[(size_t)(br + 8) * COO + co] = pack2(d[j][2], d[j][3]);
            }
        }

        gridbar(sense);

        // ================= reduce + squash (idx = b*256 + co) =================
        if (t < CC) {
            float z;
            if (it == 0) z = (float)RR;
            else {
                z = 0.f;
#pragma unroll 8
                for (int p = 0; p < NBLK; p++) z += __ldcg(&g_zpart[p * CC + t]);
            }
            a_sm[t] = z;
        }
        {
            int gg = t >> 8, ti = t & 255;
            float s = 0.f;
            if (ti < 228) {
                int idx = blk * 228 + ti;
                if (idx < BB * COO) {
                    int p0 = gg * 36;
#pragma unroll 9
                    for (int p = p0; p < p0 + 36; p++)
                        s += __ldcg(&g_spart[(size_t)p * (BB * COO) + idx]);
                }
            }
            dynf[gg * 256 + ti] = s;
        }
        __syncthreads();

        if (t < 228) {
            int idx = blk * 228 + t;
            if (idx < BB * COO) {
                float s = dynf[t] + dynf[256 + t] + dynf[512 + t] + dynf[768 + t];
                int c = (idx >> 4) & 15;
                s /= a_sm[c];
                float sn = s * s;
                float v = sn * s / ((1.f + sn) * sqrtf(sn));
                if (it == 2) {
                    out[idx] = v;
                } else {
                    int b = idx >> 8, co = idx & 255;
                    __nv_bfloat16 vh = __float2bfloat16(v);
                    g_vh[co * BB + b] = vh;
                    g_vl[co * BB + b] = __float2bfloat16(v - __bfloat162float(vh));
                }
            }
        }

        if (it < 2) gridbar(sense);
    }
}

// ---------------------------------------------------------------------------
extern "C" void kernel_launch(void* const* d_in, const int* in_sizes, int n_in,
                              void* d_out, int out_size) {
    const float* x = (const float*)d_in[0];   // [128,1152,8]
    const float* W = (const float*)d_in[1];   // [1,1152,16,16,8]
    float* out = (float*)d_out;               // [128,16,16]

    cudaFuncSetAttribute(k_persist, cudaFuncAttributeMaxDynamicSharedMemorySize, SMEM_BYTES);
    k_persist<<<NBLK, 1024, SMEM_BYTES>>>(x, W, out);
}